// round 4
// baseline (speedup 1.0000x reference)
#include <cuda_runtime.h>
#include <cstdint>

#define Bn 32
#define Cc 256
#define Hh 56
#define Wd 56
#define HW 3136
#define NPIX (Bn*HW)            // 100352
#define NELEM ((size_t)Bn*Cc*HW)
#define PD 58
#define PP (PD*PD)              // 3364

// ---------------- device scratch (no allocations allowed) ----------------
__device__ char               g_xs8[(size_t)Bn*PP*256];   // padded sign(x) s8 channel-last (27.5MB)
__device__ char               g_wb8[9*256*256];           // sign(W) s8 [tap][n][k] (589KB)
__device__ unsigned long long g_ysum[Cc];
__device__ unsigned long long g_ysumsq[Cc];
__device__ float              g_inv[Cc];
__device__ float              g_bias[Cc];
__device__ short              g_y[NELEM];                 // conv result, CHANNEL-LAST [b][pix][ch]

// ---------------- warp MMA helpers (PTX-portable, sm_75+) ----------------
__device__ __forceinline__ void ldm4(uint32_t* r, uint32_t addr) {
    asm volatile("ldmatrix.sync.aligned.m8n8.x4.shared.b16 {%0,%1,%2,%3}, [%4];"
                 : "=r"(r[0]), "=r"(r[1]), "=r"(r[2]), "=r"(r[3]) : "r"(addr));
}
__device__ __forceinline__ void imma(int* c, const uint32_t* a, uint32_t b0, uint32_t b1) {
    asm volatile("mma.sync.aligned.m16n8k32.row.col.s32.s8.s8.s32 "
                 "{%0,%1,%2,%3}, {%4,%5,%6,%7}, {%8,%9}, {%0,%1,%2,%3};"
                 : "+r"(c[0]), "+r"(c[1]), "+r"(c[2]), "+r"(c[3])
                 : "r"(a[0]), "r"(a[1]), "r"(a[2]), "r"(a[3]), "r"(b0), "r"(b1));
}
__device__ __forceinline__ uint32_t smem_u32(const void* p) {
    uint32_t a;
    asm("{ .reg .u64 t; cvta.to.shared.u64 t, %1; cvt.u32.u64 %0, t; }" : "=r"(a) : "l"(p));
    return a;
}

// ---------------------------------------------------------------------------
// Kernel 1: sign(x) -> padded channel-last s8 (+1 / -1, zeros on border)
// ---------------------------------------------------------------------------
__global__ void k_prep_x(const float* __restrict__ x) {
    int gp = blockIdx.x * 256 + threadIdx.x;
    if (gp >= Bn * PP) return;
    int b = gp / PP, pp = gp - b * PP;
    int pr = pp / PD, pc = pp - pr * PD;
    uint4* dst = (uint4*)(g_xs8 + (size_t)gp * 256);
    if (pr == 0 || pr == PD - 1 || pc == 0 || pc == PD - 1) {
        uint4 z = make_uint4(0, 0, 0, 0);
#pragma unroll
        for (int u = 0; u < 16; u++) dst[u] = z;
        return;
    }
    const float* xp = x + (size_t)b * Cc * HW + (pr - 1) * Wd + (pc - 1);
#pragma unroll
    for (int u = 0; u < 16; u++) {
        uint32_t w[4];
#pragma unroll
        for (int k2 = 0; k2 < 4; k2++) {
            uint32_t r = 0;
#pragma unroll
            for (int bb = 0; bb < 4; bb++) {
                int c = u * 16 + k2 * 4 + bb;
                uint32_t s = (xp[(size_t)c * HW] > 0.f) ? 0x01u : 0xFFu;
                r |= s << (8 * bb);
            }
            w[k2] = r;
        }
        dst[u] = make_uint4(w[0], w[1], w[2], w[3]);
    }
}

// ---------------------------------------------------------------------------
// Kernel 2: sign(W) OIHW -> s8 [tap][n][k]; zero stats
// ---------------------------------------------------------------------------
__global__ void k_prep_w(const float* __restrict__ Wt) {
    int idx = blockIdx.x * 256 + threadIdx.x;      // o*256 + i
    if (idx < Cc) { g_ysum[idx] = 0ull; g_ysumsq[idx] = 0ull; }
    if (idx >= 65536) return;
    const float* wp = Wt + (size_t)idx * 9;
#pragma unroll
    for (int t = 0; t < 9; t++)
        g_wb8[t * 65536 + idx] = (wp[t] > 0.f) ? (char)1 : (char)-1;
}

// ---------------------------------------------------------------------------
// Kernel 3: IMMA implicit-GEMM conv + fused exact BN stats
// CTA: M=256 pixels (4 output rows; 224 valid) x N=128 outch, 8 warps 64x64
// ---------------------------------------------------------------------------
#define A_STR 272                         // 256 ch + 16B pad
#define SMA   0
#define SMB0  94656                       // 6*58*272
#define SMB1  (SMB0 + 34816)              // 128*272
#define SMST  (SMB1 + 34816)              // stats: 2*128 ints
#define SMTOT (SMST + 1024)

__global__ void __launch_bounds__(256, 1) k_conv() {
    extern __shared__ char sm[];
    const uint32_t smb = smem_u32(sm);
    const int tid = threadIdx.x, wid = tid >> 5, lane = tid & 31;
    const int bx = blockIdx.x;             // 0..13 (4-row groups)
    const int half = blockIdx.y;           // N half
    const int b = blockIdx.z;

    int* ssum = (int*)(sm + SMST);         // [128] then [128] sq
    ((int*)(sm + SMST))[tid] = 0;          // tid<256 zeroes both arrays... only 256 ints
    // (256 ints total; every thread zeroes one)

    // ---- stage A: 6 padded rows x 58 pix x 256B ----
    {
        const size_t gbase = ((size_t)b * PP + bx * 4 * PD) * 256;
        for (int i = tid; i < 348 * 16; i += 256) {
            int pix = i >> 4, seg = i & 15;
            uint4 v = *(const uint4*)(g_xs8 + gbase + (size_t)pix * 256 + seg * 16);
            *(uint4*)(sm + SMA + pix * A_STR + seg * 16) = v;
        }
    }
    // ---- stage B tap0 into buf0 ----
    {
        const char* wsrc = g_wb8 + (size_t)half * 128 * 256;
        for (int i = tid; i < 128 * 16; i += 256) {
            int row = i >> 4, seg = i & 15;
            uint4 v = *(const uint4*)(wsrc + (size_t)row * 256 + seg * 16);
            *(uint4*)(sm + SMB0 + row * A_STR + seg * 16) = v;
        }
    }

    const int wm = wid & 3, wn = wid >> 2;
    const int kadd = (lane >> 4) * 16;
    // per-lane A pixel bases for 4 m-frags
    uint32_t Pm[4];
#pragma unroll
    for (int f = 0; f < 4; f++) {
        int m = wm * 64 + f * 16 + (lane & 15);
        if (m > 223) m = 223;
        Pm[f] = (uint32_t)(((m / 56) * PD + (m % 56)) * A_STR);
    }
    const uint32_t Brow = (uint32_t)((wn * 64 + (lane & 15)) * A_STR);

    int acc[4][8][4];
#pragma unroll
    for (int i = 0; i < 4; i++)
#pragma unroll
        for (int j = 0; j < 8; j++)
#pragma unroll
            for (int k = 0; k < 4; k++) acc[i][j][k] = 0;

    for (int t = 0; t < 9; t++) {
        __syncthreads();
        // prefetch next tap's B into registers
        uint4 breg[8];
        if (t < 8) {
            const char* wsrc = g_wb8 + (size_t)(t + 1) * 65536 + (size_t)half * 128 * 256;
#pragma unroll
            for (int k = 0; k < 8; k++) {
                int i = tid + k * 256;
                breg[k] = *(const uint4*)(wsrc + (size_t)(i >> 4) * 256 + (i & 15) * 16);
            }
        }
        const uint32_t tapoff = (uint32_t)(((t / 3) * PD + (t % 3)) * A_STR);
        const uint32_t abase = smb + SMA + tapoff + kadd;
        const uint32_t bbase = smb + ((t & 1) ? SMB1 : SMB0) + Brow + kadd;
#pragma unroll
        for (int q = 0; q < 8; q++) {
            uint32_t a[4][4];
#pragma unroll
            for (int f = 0; f < 4; f++) ldm4(a[f], abase + Pm[f] + q * 32);
#pragma unroll
            for (int p = 0; p < 4; p++) {
                uint32_t r[4];
                ldm4(r, bbase + p * 16 * A_STR + q * 32);
#pragma unroll
                for (int f = 0; f < 4; f++) {
                    imma(acc[f][2 * p],     a[f], r[0], r[2]);
                    imma(acc[f][2 * p + 1], a[f], r[1], r[3]);
                }
            }
        }
        if (t < 8) {
            __syncthreads();      // everyone done reading buf (t+1)&1 from tap t-1
            char* dstb = sm + ((t & 1) ? SMB0 : SMB1);
#pragma unroll
            for (int k = 0; k < 8; k++) {
                int i = tid + k * 256;
                *(uint4*)(dstb + (i >> 4) * A_STR + (i & 15) * 16) = breg[k];
            }
        }
    }
    __syncthreads();

    // ---- epilogue: store y (channel-last s16) + exact stats ----
    const int r = lane >> 2;
    const size_t pixbase = (size_t)b * HW + bx * 224;
    int p0[8], p1[8], q0[8], q1[8];
#pragma unroll
    for (int nf = 0; nf < 8; nf++) { p0[nf] = p1[nf] = q0[nf] = q1[nf] = 0; }

#pragma unroll
    for (int mf = 0; mf < 4; mf++) {
        const int mbase = wm * 64 + mf * 16;
        const bool valid = (mbase < 224);
        const int m0 = mbase + r;
#pragma unroll
        for (int nf = 0; nf < 8; nf++) {
            int v0 = acc[mf][nf][0], v1 = acc[mf][nf][1];
            int v2 = acc[mf][nf][2], v3 = acc[mf][nf][3];
            if (valid) {
                const int ch = half * 128 + wn * 64 + nf * 8 + 2 * (lane & 3);
                uint32_t lo = (uint32_t)(uint16_t)(short)v0 | ((uint32_t)(uint16_t)(short)v1 << 16);
                uint32_t hi = (uint32_t)(uint16_t)(short)v2 | ((uint32_t)(uint16_t)(short)v3 << 16);
                *(uint32_t*)(g_y + (pixbase + m0) * 256 + ch)     = lo;
                *(uint32_t*)(g_y + (pixbase + m0 + 8) * 256 + ch) = hi;
                p0[nf] += v0 + v2;  p1[nf] += v1 + v3;
                q0[nf] += v0 * v0 + v2 * v2;
                q1[nf] += v1 * v1 + v3 * v3;
            }
        }
    }
#pragma unroll
    for (int nf = 0; nf < 8; nf++) {
#pragma unroll
        for (int off = 4; off < 32; off <<= 1) {
            p0[nf] += __shfl_xor_sync(0xFFFFFFFFu, p0[nf], off);
            p1[nf] += __shfl_xor_sync(0xFFFFFFFFu, p1[nf], off);
            q0[nf] += __shfl_xor_sync(0xFFFFFFFFu, q0[nf], off);
            q1[nf] += __shfl_xor_sync(0xFFFFFFFFu, q1[nf], off);
        }
        if (lane < 4) {
            int cloc = wn * 64 + nf * 8 + 2 * lane;
            atomicAdd(&ssum[cloc],       p0[nf]);
            atomicAdd(&ssum[cloc + 1],   p1[nf]);
            atomicAdd(&ssum[128 + cloc],     q0[nf]);
            atomicAdd(&ssum[128 + cloc + 1], q1[nf]);
        }
    }
    __syncthreads();
    if (tid < 128) {
        int ch = half * 128 + tid;
        atomicAdd(&g_ysum[ch],   (unsigned long long)(long long)ssum[tid]);
        atomicAdd(&g_ysumsq[ch], (unsigned long long)(long long)ssum[128 + tid]);
    }
}

// ---------------------------------------------------------------------------
// Kernel 4: finalize BN constants
// ---------------------------------------------------------------------------
__global__ void k_finalize(const float* __restrict__ gamma,
                           const float* __restrict__ beta) {
    int c = threadIdx.x;
    const double n = (double)NPIX;
    double mean = (double)(long long)g_ysum[c] / n;
    double var  = (double)(long long)g_ysumsq[c] / n - mean * mean;
    float inv = gamma[c] / sqrtf((float)var + 1e-5f);
    g_inv[c]  = inv;
    g_bias[c] = beta[c] - (float)mean * inv;
}

// ---------------------------------------------------------------------------
// Kernel 5: BN apply + residual; y is channel-last -> transpose via smem
// block: 32 pixels x 256 ch
// ---------------------------------------------------------------------------
__global__ void k_bn_add(const float* __restrict__ x, float* __restrict__ out) {
    __shared__ uint32_t st[32][128];
    const int tid = threadIdx.x;
    const int b  = blockIdx.x / 98;
    const int p0 = (blockIdx.x % 98) * 32;

    // load y tile coalesced, XOR-swizzled store
    const uint32_t* ysrc = (const uint32_t*)(g_y + ((size_t)b * HW + p0) * 256);
#pragma unroll
    for (int k = 0; k < 16; k++) {
        int idx = tid + k * 256;               // 4096 words
        int p = idx >> 7, chw = idx & 127;
        st[p][chw ^ p] = ysrc[idx];
    }
    __syncthreads();

    const int wrp = tid >> 5, lanep = tid & 31;
#pragma unroll 4
    for (int it = 0; it < 32; it++) {
        int c = it * 8 + wrp;
        float inv = g_inv[c], bias = g_bias[c];
        uint32_t wv = st[lanep][(c >> 1) ^ lanep];
        short v = (c & 1) ? (short)(wv >> 16) : (short)(wv & 0xFFFF);
        size_t gi = ((size_t)b * Cc + c) * HW + p0 + lanep;
        out[gi] = (float)v * inv + bias + x[gi];
    }
}

// ---------------------------------------------------------------------------
extern "C" void kernel_launch(void* const* d_in, const int* in_sizes, int n_in,
                              void* d_out, int out_size) {
    const float* x     = (const float*)d_in[0];
    const float* Wt    = (const float*)d_in[1];
    const float* gamma = (const float*)d_in[2];
    const float* beta  = (const float*)d_in[3];
    float* out = (float*)d_out;

    static int smset = 0;
    if (!smset) {
        cudaFuncSetAttribute(k_conv, cudaFuncAttributeMaxDynamicSharedMemorySize, SMTOT);
        smset = 1;
    }

    k_prep_x<<<(Bn * PP + 255) / 256, 256>>>(x);
    k_prep_w<<<256, 256>>>(Wt);
    k_conv<<<dim3(14, 2, Bn), 256, SMTOT>>>();
    k_finalize<<<1, Cc>>>(gamma, beta);
    k_bn_add<<<NPIX / 32, 256>>>(x, out);
}

// round 5
// speedup vs baseline: 1.0137x; 1.0137x over previous
#include <cuda_runtime.h>
#include <cstdint>

#define Bn 32
#define Cc 256
#define Hh 56
#define Wd 56
#define HW 3136
#define NPIX (Bn*HW)            // 100352
#define NELEM ((size_t)Bn*Cc*HW)
#define PD 58
#define PP (PD*PD)              // 3364

// ---------------- device scratch (no allocations allowed) ----------------
__device__ char               g_xs8[(size_t)Bn*PP*256];   // padded sign(x) s8 channel-last (27.5MB)
__device__ char               g_wb8[9*256*256];           // sign(W) s8 [tap][n][k] (589KB)
__device__ unsigned long long g_ysum[Cc];
__device__ unsigned long long g_ysumsq[Cc];
__device__ short              g_y[NELEM];                 // conv result, CHANNEL-LAST [b][pix][ch]

// ---------------- PTX helpers (portable, sm_80+) ----------------
__device__ __forceinline__ void ldm4(uint32_t* r, uint32_t addr) {
    asm volatile("ldmatrix.sync.aligned.m8n8.x4.shared.b16 {%0,%1,%2,%3}, [%4];"
                 : "=r"(r[0]), "=r"(r[1]), "=r"(r[2]), "=r"(r[3]) : "r"(addr));
}
__device__ __forceinline__ void imma(int* c, const uint32_t* a, uint32_t b0, uint32_t b1) {
    asm volatile("mma.sync.aligned.m16n8k32.row.col.s32.s8.s8.s32 "
                 "{%0,%1,%2,%3}, {%4,%5,%6,%7}, {%8,%9}, {%0,%1,%2,%3};"
                 : "+r"(c[0]), "+r"(c[1]), "+r"(c[2]), "+r"(c[3])
                 : "r"(a[0]), "r"(a[1]), "r"(a[2]), "r"(a[3]), "r"(b0), "r"(b1));
}
__device__ __forceinline__ uint32_t smem_u32(const void* p) {
    uint32_t a;
    asm("{ .reg .u64 t; cvta.to.shared.u64 t, %1; cvt.u32.u64 %0, t; }" : "=r"(a) : "l"(p));
    return a;
}
__device__ __forceinline__ void cpa16(uint32_t dst, const void* src) {
    asm volatile("cp.async.cg.shared.global [%0], [%1], 16;" :: "r"(dst), "l"(src));
}
#define CPA_COMMIT() asm volatile("cp.async.commit_group;" ::: "memory")
#define CPA_WAIT0()  asm volatile("cp.async.wait_group 0;" ::: "memory")

// ---------------------------------------------------------------------------
// Kernel 1: sign(x) -> padded channel-last s8 (+1 / -1, zeros on border)
// ---------------------------------------------------------------------------
__global__ void k_prep_x(const float* __restrict__ x) {
    int gp = blockIdx.x * 256 + threadIdx.x;
    if (gp >= Bn * PP) return;
    int b = gp / PP, pp = gp - b * PP;
    int pr = pp / PD, pc = pp - pr * PD;
    uint4* dst = (uint4*)(g_xs8 + (size_t)gp * 256);
    if (pr == 0 || pr == PD - 1 || pc == 0 || pc == PD - 1) {
        uint4 z = make_uint4(0, 0, 0, 0);
#pragma unroll
        for (int u = 0; u < 16; u++) dst[u] = z;
        return;
    }
    const float* xp = x + (size_t)b * Cc * HW + (pr - 1) * Wd + (pc - 1);
#pragma unroll
    for (int u = 0; u < 16; u++) {
        uint32_t w[4];
#pragma unroll
        for (int k2 = 0; k2 < 4; k2++) {
            uint32_t r = 0;
#pragma unroll
            for (int bb = 0; bb < 4; bb++) {
                int c = u * 16 + k2 * 4 + bb;
                uint32_t s = (xp[(size_t)c * HW] > 0.f) ? 0x01u : 0xFFu;
                r |= s << (8 * bb);
            }
            w[k2] = r;
        }
        dst[u] = make_uint4(w[0], w[1], w[2], w[3]);
    }
}

// ---------------------------------------------------------------------------
// Kernel 2: sign(W) OIHW -> s8 [tap][n][k]; zero stats
// ---------------------------------------------------------------------------
__global__ void k_prep_w(const float* __restrict__ Wt) {
    int idx = blockIdx.x * 256 + threadIdx.x;      // o*256 + i
    if (idx < Cc) { g_ysum[idx] = 0ull; g_ysumsq[idx] = 0ull; }
    if (idx >= 65536) return;
    const float* wp = Wt + (size_t)idx * 9;
#pragma unroll
    for (int t = 0; t < 9; t++)
        g_wb8[t * 65536 + idx] = (wp[t] > 0.f) ? (char)1 : (char)-1;
}

// ---------------------------------------------------------------------------
// Kernel 3: IMMA implicit-GEMM conv + fused exact BN stats
// CTA: M=256 pixels (4 output rows; 224 valid) x N=128 outch, 8 warps 64x64
// B double-buffered via cp.async (no register staging)
// ---------------------------------------------------------------------------
#define A_STR 272                         // 256 ch + 16B pad
#define SMA   0
#define SMB0  94656                       // 6*58*272
#define SMB1  (SMB0 + 34816)              // 128*272
#define SMST  (SMB1 + 34816)              // stats: 2*128 ints
#define SMTOT (SMST + 1024)

__global__ void __launch_bounds__(256, 1) k_conv() {
    extern __shared__ char sm[];
    const uint32_t smb = smem_u32(sm);
    const int tid = threadIdx.x, wid = tid >> 5, lane = tid & 31;
    const int bx = blockIdx.x;             // 0..13 (4-row groups)
    const int half = blockIdx.y;           // N half
    const int b = blockIdx.z;

    int* ssum = (int*)(sm + SMST);
    ssum[tid] = 0;                         // zero 256 ints (sum + sq arrays)

    // ---- stage A (6 padded rows x 58 pix x 256B) + B tap0 via cp.async ----
    {
        const char* gA = g_xs8 + ((size_t)b * PP + bx * 4 * PD) * 256;
        for (int i = tid; i < 348 * 16; i += 256)
            cpa16(smb + SMA + (i >> 4) * A_STR + (i & 15) * 16,
                  gA + (size_t)(i >> 4) * 256 + (i & 15) * 16);
        const char* wsrc = g_wb8 + (size_t)half * 128 * 256;
        for (int i = tid; i < 128 * 16; i += 256)
            cpa16(smb + SMB0 + (i >> 4) * A_STR + (i & 15) * 16,
                  wsrc + (size_t)(i >> 4) * 256 + (i & 15) * 16);
        CPA_COMMIT();
    }

    const int wm = wid & 3, wn = wid >> 2;
    const int kadd = (lane >> 4) * 16;
    uint32_t Pm[4];
#pragma unroll
    for (int f = 0; f < 4; f++) {
        int m = wm * 64 + f * 16 + (lane & 15);
        if (m > 223) m = 223;
        Pm[f] = (uint32_t)(((m / 56) * PD + (m % 56)) * A_STR);
    }
    const uint32_t Brow = (uint32_t)((wn * 64 + (lane & 15)) * A_STR);

    int acc[4][8][4];
#pragma unroll
    for (int i = 0; i < 4; i++)
#pragma unroll
        for (int j = 0; j < 8; j++)
#pragma unroll
            for (int k = 0; k < 4; k++) acc[i][j][k] = 0;

    CPA_WAIT0();
    __syncthreads();

    for (int t = 0; t < 9; t++) {
        // issue next tap's B into the other buffer (overlaps this tap's MMA)
        if (t < 8) {
            const char* wsrc = g_wb8 + (size_t)(t + 1) * 65536 + (size_t)half * 128 * 256;
            const uint32_t dstb = smb + (((t + 1) & 1) ? SMB1 : SMB0);
            for (int i = tid; i < 128 * 16; i += 256)
                cpa16(dstb + (i >> 4) * A_STR + (i & 15) * 16,
                      wsrc + (size_t)(i >> 4) * 256 + (i & 15) * 16);
            CPA_COMMIT();
        }

        const uint32_t tapoff = (uint32_t)(((t / 3) * PD + (t % 3)) * A_STR);
        const uint32_t abase = smb + SMA + tapoff + kadd;
        const uint32_t bbase = smb + ((t & 1) ? SMB1 : SMB0) + Brow + kadd;
#pragma unroll
        for (int q = 0; q < 8; q++) {
            uint32_t a[4][4];
#pragma unroll
            for (int f = 0; f < 4; f++) ldm4(a[f], abase + Pm[f] + q * 32);
#pragma unroll
            for (int p = 0; p < 4; p++) {
                uint32_t r[4];
                ldm4(r, bbase + p * 16 * A_STR + q * 32);
#pragma unroll
                for (int f = 0; f < 4; f++) {
                    imma(acc[f][2 * p],     a[f], r[0], r[2]);
                    imma(acc[f][2 * p + 1], a[f], r[1], r[3]);
                }
            }
        }
        if (t < 8) { CPA_WAIT0(); }
        __syncthreads();
    }

    // ---- epilogue: store y (channel-last s16) + exact stats ----
    const int r = lane >> 2;
    const size_t pixbase = (size_t)b * HW + bx * 224;
    int p0[8], p1[8], q0[8], q1[8];
#pragma unroll
    for (int nf = 0; nf < 8; nf++) { p0[nf] = p1[nf] = q0[nf] = q1[nf] = 0; }

#pragma unroll
    for (int mf = 0; mf < 4; mf++) {
        const int mbase = wm * 64 + mf * 16;
        const bool valid = (mbase < 224);
        const int m0 = mbase + r;
#pragma unroll
        for (int nf = 0; nf < 8; nf++) {
            int v0 = acc[mf][nf][0], v1 = acc[mf][nf][1];
            int v2 = acc[mf][nf][2], v3 = acc[mf][nf][3];
            if (valid) {
                const int ch = half * 128 + wn * 64 + nf * 8 + 2 * (lane & 3);
                uint32_t lo = (uint32_t)(uint16_t)(short)v0 | ((uint32_t)(uint16_t)(short)v1 << 16);
                uint32_t hi = (uint32_t)(uint16_t)(short)v2 | ((uint32_t)(uint16_t)(short)v3 << 16);
                *(uint32_t*)(g_y + (pixbase + m0) * 256 + ch)     = lo;
                *(uint32_t*)(g_y + (pixbase + m0 + 8) * 256 + ch) = hi;
                p0[nf] += v0 + v2;  p1[nf] += v1 + v3;
                q0[nf] += v0 * v0 + v2 * v2;
                q1[nf] += v1 * v1 + v3 * v3;
            }
        }
    }
#pragma unroll
    for (int nf = 0; nf < 8; nf++) {
#pragma unroll
        for (int off = 4; off < 32; off <<= 1) {
            p0[nf] += __shfl_xor_sync(0xFFFFFFFFu, p0[nf], off);
            p1[nf] += __shfl_xor_sync(0xFFFFFFFFu, p1[nf], off);
            q0[nf] += __shfl_xor_sync(0xFFFFFFFFu, q0[nf], off);
            q1[nf] += __shfl_xor_sync(0xFFFFFFFFu, q1[nf], off);
        }
        if (lane < 4) {
            int cloc = wn * 64 + nf * 8 + 2 * lane;
            atomicAdd(&ssum[cloc],           p0[nf]);
            atomicAdd(&ssum[cloc + 1],       p1[nf]);
            atomicAdd(&ssum[128 + cloc],     q0[nf]);
            atomicAdd(&ssum[128 + cloc + 1], q1[nf]);
        }
    }
    __syncthreads();
    if (tid < 128) {
        int ch = half * 128 + tid;
        atomicAdd(&g_ysum[ch],   (unsigned long long)(long long)ssum[tid]);
        atomicAdd(&g_ysumsq[ch], (unsigned long long)(long long)ssum[128 + tid]);
    }
}

// ---------------------------------------------------------------------------
// Kernel 4: BN finalize (per-block, cheap) + apply + residual.
// y is channel-last -> transpose via smem. block: 32 pixels x 256 ch
// ---------------------------------------------------------------------------
__global__ void k_bn_add(const float* __restrict__ x,
                         const float* __restrict__ gamma,
                         const float* __restrict__ beta,
                         float* __restrict__ out) {
    __shared__ uint32_t st[32][128];
    __shared__ float sinv[256], sbias[256];
    const int tid = threadIdx.x;
    const int b  = blockIdx.x / 98;
    const int p0 = (blockIdx.x % 98) * 32;

    {   // recompute BN constants (reads 4 scalars; ~free)
        const double n = (double)NPIX;
        double mean = (double)(long long)g_ysum[tid] / n;
        double var  = (double)(long long)g_ysumsq[tid] / n - mean * mean;
        float inv = gamma[tid] / sqrtf((float)var + 1e-5f);
        sinv[tid]  = inv;
        sbias[tid] = beta[tid] - (float)mean * inv;
    }

    const uint32_t* ysrc = (const uint32_t*)(g_y + ((size_t)b * HW + p0) * 256);
#pragma unroll
    for (int k = 0; k < 16; k++) {
        int idx = tid + k * 256;
        int p = idx >> 7, chw = idx & 127;
        st[p][chw ^ p] = ysrc[idx];
    }
    __syncthreads();

    const int wrp = tid >> 5, lanep = tid & 31;
#pragma unroll 4
    for (int it = 0; it < 32; it++) {
        int c = it * 8 + wrp;
        float inv = sinv[c], bias = sbias[c];
        uint32_t wv = st[lanep][(c >> 1) ^ lanep];
        short v = (c & 1) ? (short)(wv >> 16) : (short)(wv & 0xFFFF);
        size_t gi = ((size_t)b * Cc + c) * HW + p0 + lanep;
        out[gi] = (float)v * inv + bias + x[gi];
    }
}

// ---------------------------------------------------------------------------
extern "C" void kernel_launch(void* const* d_in, const int* in_sizes, int n_in,
                              void* d_out, int out_size) {
    const float* x     = (const float*)d_in[0];
    const float* Wt    = (const float*)d_in[1];
    const float* gamma = (const float*)d_in[2];
    const float* beta  = (const float*)d_in[3];
    float* out = (float*)d_out;

    static int smset = 0;
    if (!smset) {
        cudaFuncSetAttribute(k_conv, cudaFuncAttributeMaxDynamicSharedMemorySize, SMTOT);
        smset = 1;
    }

    k_prep_x<<<(Bn * PP + 255) / 256, 256>>>(x);
    k_prep_w<<<256, 256>>>(Wt);
    k_conv<<<dim3(14, 2, Bn), 256, SMTOT>>>();
    k_bn_add<<<NPIX / 32, 256>>>(x, gamma, beta, out);
}

// round 7
// speedup vs baseline: 2.3602x; 2.3283x over previous
#include <cuda_runtime.h>
#include <cstdint>

#define Bn 32
#define Cc 256
#define Hh 56
#define Wd 56
#define HW 3136
#define NPIX (Bn*HW)
#define NELEM ((size_t)Bn*Cc*HW)

// ---- device scratch ----
__device__ uint4              g_xbits[NPIX * 2];        // 8 u32 per pixel
__device__ uint32_t           g_wbits[Cc * 9 * 8];      // [o][tap][8]
__device__ int                g_ctab[9 * Cc];           // [cfg][o] border corrections
__device__ unsigned long long g_ysum[Cc];
__device__ unsigned long long g_ysumsq[Cc];
__device__ short              g_y[NELEM];               // NCHW int16 conv result

__device__ __forceinline__ void FAf(uint32_t a, uint32_t b, uint32_t c,
                                    uint32_t& s, uint32_t& cy) {
    uint32_t t = a ^ b;
    s  = t ^ c;
    cy = (a & b) | (c & t);
}
__device__ __forceinline__ void HAf(uint32_t a, uint32_t b,
                                    uint32_t& s, uint32_t& cy) {
    s = a ^ b; cy = a & b;
}

// ---------------------------------------------------------------------------
// Kernel 1: binarize x (NCHW) -> per-pixel 256-bit vectors
// ---------------------------------------------------------------------------
__global__ void k_binarize_x(const float* __restrict__ x) {
    int gp = blockIdx.x * 256 + threadIdx.x;
    if (gp >= NPIX) return;
    int b = gp / HW;
    int p = gp - b * HW;
    const float* xp = x + (size_t)b * Cc * HW + p;
    uint32_t wrd[8];
#pragma unroll
    for (int j = 0; j < 8; j++) {
        uint32_t v = 0;
#pragma unroll
        for (int l = 0; l < 32; l++) {
            float f = xp[(size_t)(j * 32 + l) * HW];
            v |= (f > 0.0f ? 1u : 0u) << l;
        }
        wrd[j] = v;
    }
    g_xbits[gp * 2 + 0] = make_uint4(wrd[0], wrd[1], wrd[2], wrd[3]);
    g_xbits[gp * 2 + 1] = make_uint4(wrd[4], wrd[5], wrd[6], wrd[7]);
}

// ---------------------------------------------------------------------------
// Kernel 2: binarize W (OIHW) + zero stat accumulators
// ---------------------------------------------------------------------------
__global__ void k_binarize_w(const float* __restrict__ Wt) {
    int idx = blockIdx.x * 256 + threadIdx.x;
    if (idx < Cc) { g_ysum[idx] = 0ull; g_ysumsq[idx] = 0ull; }
    if (idx >= Cc * 9 * 8) return;
    int j   = idx & 7;
    int tap = (idx >> 3) % 9;
    int o   = idx / 72;
    uint32_t v = 0;
#pragma unroll
    for (int l = 0; l < 32; l++) {
        int i = j * 32 + l;
        float f = Wt[((size_t)o * Cc + i) * 9 + tap];
        v |= (f > 0.0f ? 1u : 0u) << l;
    }
    g_wbits[idx] = v;
}

// ---------------------------------------------------------------------------
// Kernel 2b: per (border-config, outch) correction table
// C[cfg][o] = sum of popc(w_tap) over taps invalid under cfg
// ---------------------------------------------------------------------------
__global__ void k_prep_c() {
    int o = threadIdx.x;
    int ct[9];
#pragma unroll
    for (int t = 0; t < 9; t++) {
        int s = 0;
#pragma unroll
        for (int j = 0; j < 8; j++) s += __popc(g_wbits[o * 72 + t * 8 + j]);
        ct[t] = s;
    }
#pragma unroll
    for (int cfg = 0; cfg < 9; cfg++) {
        int rcf = cfg / 3, ccf = cfg % 3;
        int Cv = 0;
#pragma unroll
        for (int t = 0; t < 9; t++) {
            int kh = t / 3, kw = t % 3;
            bool inv = (rcf == 0 && kh == 0) || (rcf == 2 && kh == 2) ||
                       (ccf == 0 && kw == 0) || (ccf == 2 && kw == 2);
            if (inv) Cv += ct[t];
        }
        g_ctab[cfg * Cc + o] = Cv;
    }
}

// ---------------------------------------------------------------------------
// Kernel 3: XNOR conv via CSA-compressed popcount
// Block = 256 pixels x 128 outch loop; x bits in regs, w from smem
// ---------------------------------------------------------------------------
__global__ void __launch_bounds__(256, 1) k_conv() {
    const int p    = blockIdx.x * 256 + threadIdx.x;
    const int half = blockIdx.y;
    const int b    = blockIdx.z;

    __shared__ uint4 ws4[128 * 18];       // 36 KB weights
    __shared__ int   sC[9 * 257];         // corrections (stride 257)
    {
        const uint4* src = (const uint4*)(g_wbits + half * 128 * 72);
        for (int i = threadIdx.x; i < 128 * 18; i += 256) ws4[i] = src[i];
        for (int i = threadIdx.x; i < 9 * 256; i += 256)
            sC[(i >> 8) * 257 + (i & 255)] = g_ctab[i];
    }
    __syncthreads();
    if (p >= HW) return;

    const int h = p / Wd;
    const int w = p - h * Wd;
    const int rcf = (h == 0) ? 0 : ((h == Hh - 1) ? 2 : 1);
    const int ccf = (w == 0) ? 0 : ((w == Wd - 1) ? 2 : 1);
    const int cfg = rcf * 3 + ccf;
    const int nvbase = 256 * (((rcf == 1) ? 3 : 2) * ((ccf == 1) ? 3 : 2));
    const int cbase = cfg * 257 + half * 128;     // FIX: global-channel correction

    // x neighborhood -> 72 regs (zero words for invalid taps)
    uint32_t xr[72];
#pragma unroll
    for (int kh = 0; kh < 3; kh++) {
#pragma unroll
        for (int kw = 0; kw < 3; kw++) {
            const int tap = kh * 3 + kw;
            const int hh = h + kh - 1, ww = w + kw - 1;
            const bool v = ((unsigned)hh < (unsigned)Hh) && ((unsigned)ww < (unsigned)Wd);
            if (v) {
                const uint4 a0 = g_xbits[(b * HW + hh * Wd + ww) * 2 + 0];
                const uint4 a1 = g_xbits[(b * HW + hh * Wd + ww) * 2 + 1];
                xr[tap * 8 + 0] = a0.x; xr[tap * 8 + 1] = a0.y;
                xr[tap * 8 + 2] = a0.z; xr[tap * 8 + 3] = a0.w;
                xr[tap * 8 + 4] = a1.x; xr[tap * 8 + 5] = a1.y;
                xr[tap * 8 + 6] = a1.z; xr[tap * 8 + 7] = a1.w;
            } else {
#pragma unroll
                for (int j = 0; j < 8; j++) xr[tap * 8 + j] = 0u;
            }
        }
    }

    short* yout = g_y + ((size_t)(b * Cc + half * 128)) * HW + p;

#pragma unroll 1
    for (int o = 0; o < 128; o++) {
        uint32_t wv[72];
        const uint4* wp = ws4 + o * 18;
#pragma unroll
        for (int j = 0; j < 18; j++) {
            const uint4 v = wp[j];
            wv[4 * j] = v.x; wv[4 * j + 1] = v.y; wv[4 * j + 2] = v.z; wv[4 * j + 3] = v.w;
        }

        // ---- CSA popcount of the 72 xor words ----
        uint32_t s[24], c[24];
#pragma unroll
        for (int g = 0; g < 24; g++)
            FAf(xr[3 * g] ^ wv[3 * g], xr[3 * g + 1] ^ wv[3 * g + 1],
                xr[3 * g + 2] ^ wv[3 * g + 2], s[g], c[g]);
        uint32_t t1[8], d2[8];
#pragma unroll
        for (int g = 0; g < 8; g++) FAf(s[3 * g], s[3 * g + 1], s[3 * g + 2], t1[g], d2[g]);
        uint32_t u0, u1, u2, e0, e1, e2, e3, W1;
        FAf(t1[0], t1[1], t1[2], u0, e0);
        FAf(t1[3], t1[4], t1[5], u1, e1);
        HAf(t1[6], t1[7], u2, e2);
        FAf(u0, u1, u2, W1, e3);
        // weight-2 pool (36)
        uint32_t q[36];
#pragma unroll
        for (int i = 0; i < 24; i++) q[i] = c[i];
#pragma unroll
        for (int i = 0; i < 8; i++) q[24 + i] = d2[i];
        q[32] = e0; q[33] = e1; q[34] = e2; q[35] = e3;
        uint32_t f[12], g4[18];
#pragma unroll
        for (int i = 0; i < 12; i++) FAf(q[3 * i], q[3 * i + 1], q[3 * i + 2], f[i], g4[i]);
        uint32_t f2[4];
#pragma unroll
        for (int i = 0; i < 4; i++) FAf(f[3 * i], f[3 * i + 1], f[3 * i + 2], f2[i], g4[12 + i]);
        uint32_t f3, W2;
        FAf(f2[0], f2[1], f2[2], f3, g4[16]);
        HAf(f3, f2[3], W2, g4[17]);
        // weight-4 pool (18)
        uint32_t hh2[6], i8[9];
#pragma unroll
        for (int i = 0; i < 6; i++) FAf(g4[3 * i], g4[3 * i + 1], g4[3 * i + 2], hh2[i], i8[i]);
        uint32_t h2a, h2b, W4;
        FAf(hh2[0], hh2[1], hh2[2], h2a, i8[6]);
        FAf(hh2[3], hh2[4], hh2[5], h2b, i8[7]);
        HAf(h2a, h2b, W4, i8[8]);
        // weight-8 pool (9)
        uint32_t j3[3], k16[5];
#pragma unroll
        for (int i = 0; i < 3; i++) FAf(i8[3 * i], i8[3 * i + 1], i8[3 * i + 2], j3[i], k16[i]);
        uint32_t W8;
        FAf(j3[0], j3[1], j3[2], W8, k16[3]);
        // weight-16 pool (4)
        uint32_t m0, l32a, W16, l32b, W32, W64;
        FAf(k16[0], k16[1], k16[2], m0, l32a);
        HAf(m0, k16[3], W16, l32b);
        HAf(l32a, l32b, W32, W64);

        int P = __popc(W1) + (__popc(W2) << 1) + (__popc(W4) << 2) + (__popc(W8) << 3)
              + (__popc(W16) << 4) + (__popc(W32) << 5) + (__popc(W64) << 6);
        int y = nvbase + 2 * sC[cbase + o] - 2 * P;
        yout[(size_t)o * HW] = (short)y;
    }
}

// ---------------------------------------------------------------------------
// Kernel 3b: BN statistics over y (exact integer sums)
// ---------------------------------------------------------------------------
__global__ void k_stats() {
    const int c = blockIdx.x, b = blockIdx.y;
    const int4* yp = (const int4*)(g_y + ((size_t)(b * Cc + c)) * HW);
    int       s  = 0;
    long long sq = 0;
    for (int i = threadIdx.x; i < HW / 8; i += 256) {
        int4 v = yp[i];
        const int ww[4] = {v.x, v.y, v.z, v.w};
#pragma unroll
        for (int j = 0; j < 4; j++) {
            int lo = (short)(ww[j] & 0xFFFF);
            int hi = (short)(((unsigned)ww[j]) >> 16);
            s  += lo + hi;
            sq += (long long)lo * lo + (long long)hi * hi;
        }
    }
#pragma unroll
    for (int off = 16; off > 0; off >>= 1) {
        s  += __shfl_down_sync(0xFFFFFFFFu, s,  off);
        sq += __shfl_down_sync(0xFFFFFFFFu, sq, off);
    }
    __shared__ int       wsum[8];
    __shared__ long long wsq[8];
    const int lane = threadIdx.x & 31, wid = threadIdx.x >> 5;
    if (lane == 0) { wsum[wid] = s; wsq[wid] = sq; }
    __syncthreads();
    if (wid == 0) {
        int       s2  = (lane < 8) ? wsum[lane] : 0;
        long long sq2 = (lane < 8) ? wsq[lane]  : 0;
#pragma unroll
        for (int off = 4; off > 0; off >>= 1) {
            s2  += __shfl_down_sync(0xFFFFFFFFu, s2,  off);
            sq2 += __shfl_down_sync(0xFFFFFFFFu, sq2, off);
        }
        if (lane == 0) {
            atomicAdd(&g_ysum[c],   (unsigned long long)(long long)s2);
            atomicAdd(&g_ysumsq[c], (unsigned long long)sq2);
        }
    }
}

// ---------------------------------------------------------------------------
// Kernel 4: BN finalize (inline) + apply + residual, vec4
// ---------------------------------------------------------------------------
__global__ void k_bn_add(const float* __restrict__ x,
                         const float* __restrict__ gamma,
                         const float* __restrict__ beta,
                         float* __restrict__ out) {
    size_t i4 = (size_t)blockIdx.x * 256 + threadIdx.x;
    if (i4 >= NELEM / 4) return;
    size_t base = i4 * 4;
    int c = (int)((base / HW) % Cc);
    const float ninv = 1.0f / (float)NPIX;
    float mean = (float)(long long)g_ysum[c] * ninv;
    float var  = (float)(long long)g_ysumsq[c] * ninv - mean * mean;
    float inv  = gamma[c] * rsqrtf(var + 1e-5f);
    float bias = beta[c] - mean * inv;
    short4 ys = ((const short4*)g_y)[i4];
    float4 xv = ((const float4*)x)[i4];
    float4 ov;
    ov.x = (float)ys.x * inv + bias + xv.x;
    ov.y = (float)ys.y * inv + bias + xv.y;
    ov.z = (float)ys.z * inv + bias + xv.z;
    ov.w = (float)ys.w * inv + bias + xv.w;
    ((float4*)out)[i4] = ov;
}

// ---------------------------------------------------------------------------
extern "C" void kernel_launch(void* const* d_in, const int* in_sizes, int n_in,
                              void* d_out, int out_size) {
    const float* x     = (const float*)d_in[0];
    const float* Wt    = (const float*)d_in[1];
    const float* gamma = (const float*)d_in[2];
    const float* beta  = (const float*)d_in[3];
    float* out = (float*)d_out;

    k_binarize_x<<<(NPIX + 255) / 256, 256>>>(x);
    k_binarize_w<<<(Cc * 9 * 8 + 255) / 256, 256>>>(Wt);
    k_prep_c<<<1, 256>>>();
    k_conv<<<dim3((HW + 255) / 256, 2, Bn), 256>>>();
    k_stats<<<dim3(Cc, Bn), 256>>>();
    k_bn_add<<<(unsigned)((NELEM / 4 + 255) / 256), 256>>>(x, gamma, beta, out);
}

// round 8
// speedup vs baseline: 2.8147x; 1.1925x over previous
#include <cuda_runtime.h>
#include <cstdint>

#define Bn 32
#define Cc 256
#define Hh 56
#define Wd 56
#define HW 3136
#define NPIX (Bn*HW)
#define NELEM ((size_t)Bn*Cc*HW)

// ---- device scratch ----
__device__ uint4              g_xbits[NPIX * 2];        // 8 u32 per pixel
__device__ uint32_t           g_wbits[Cc * 9 * 8];      // [o][tap][8]
__device__ int                g_ctab[9 * Cc];           // [cfg][o] border corrections
__device__ unsigned long long g_ysum[Cc];
__device__ unsigned long long g_ysumsq[Cc];
__device__ short              g_y[NELEM];               // NCHW int16 conv result

__device__ __forceinline__ void FAf(uint32_t a, uint32_t b, uint32_t c,
                                    uint32_t& s, uint32_t& cy) {
    s  = a ^ b ^ c;
    cy = (a & b) | (c & (a ^ b));
}
__device__ __forceinline__ void HAf(uint32_t a, uint32_t b,
                                    uint32_t& s, uint32_t& cy) {
    s = a ^ b; cy = a & b;
}

// ---------------------------------------------------------------------------
// Kernel 1: binarize x (NCHW) -> per-pixel 256-bit vectors
// ---------------------------------------------------------------------------
__global__ void k_binarize_x(const float* __restrict__ x) {
    int gp = blockIdx.x * 256 + threadIdx.x;
    if (gp >= NPIX) return;
    int b = gp / HW;
    int p = gp - b * HW;
    const float* xp = x + (size_t)b * Cc * HW + p;
    uint32_t wrd[8];
#pragma unroll
    for (int j = 0; j < 8; j++) {
        uint32_t v = 0;
#pragma unroll
        for (int l = 0; l < 32; l++) {
            float f = xp[(size_t)(j * 32 + l) * HW];
            v |= (f > 0.0f ? 1u : 0u) << l;
        }
        wrd[j] = v;
    }
    g_xbits[gp * 2 + 0] = make_uint4(wrd[0], wrd[1], wrd[2], wrd[3]);
    g_xbits[gp * 2 + 1] = make_uint4(wrd[4], wrd[5], wrd[6], wrd[7]);
}

// ---------------------------------------------------------------------------
// Kernel 2: binarize W (OIHW) + zero stat accumulators
// ---------------------------------------------------------------------------
__global__ void k_binarize_w(const float* __restrict__ Wt) {
    int idx = blockIdx.x * 256 + threadIdx.x;
    if (idx < Cc) { g_ysum[idx] = 0ull; g_ysumsq[idx] = 0ull; }
    if (idx >= Cc * 9 * 8) return;
    int j   = idx & 7;
    int tap = (idx >> 3) % 9;
    int o   = idx / 72;
    uint32_t v = 0;
#pragma unroll
    for (int l = 0; l < 32; l++) {
        int i = j * 32 + l;
        float f = Wt[((size_t)o * Cc + i) * 9 + tap];
        v |= (f > 0.0f ? 1u : 0u) << l;
    }
    g_wbits[idx] = v;
}

// ---------------------------------------------------------------------------
// Kernel 2b: per (border-config, outch) correction table
// ---------------------------------------------------------------------------
__global__ void k_prep_c() {
    int o = threadIdx.x;
    int ct[9];
#pragma unroll
    for (int t = 0; t < 9; t++) {
        int s = 0;
#pragma unroll
        for (int j = 0; j < 8; j++) s += __popc(g_wbits[o * 72 + t * 8 + j]);
        ct[t] = s;
    }
#pragma unroll
    for (int cfg = 0; cfg < 9; cfg++) {
        int rcf = cfg / 3, ccf = cfg % 3;
        int Cv = 0;
#pragma unroll
        for (int t = 0; t < 9; t++) {
            int kh = t / 3, kw = t % 3;
            bool inv = (rcf == 0 && kh == 0) || (rcf == 2 && kh == 2) ||
                       (ccf == 0 && kw == 0) || (ccf == 2 && kw == 2);
            if (inv) Cv += ct[t];
        }
        g_ctab[cfg * Cc + o] = Cv;
    }
}

// ---------------------------------------------------------------------------
// Kernel 3: XNOR conv — hybrid direct-POPC (taps 0..3) + CSA (taps 4..8)
// ---------------------------------------------------------------------------
__global__ void __launch_bounds__(256, 1) k_conv() {
    const int p    = blockIdx.x * 256 + threadIdx.x;
    const int half = blockIdx.y;
    const int b    = blockIdx.z;

    __shared__ uint4 ws4[128 * 18];
    __shared__ int   sC[9 * 257];
    {
        const uint4* src = (const uint4*)(g_wbits + half * 128 * 72);
        for (int i = threadIdx.x; i < 128 * 18; i += 256) ws4[i] = src[i];
        for (int i = threadIdx.x; i < 9 * 256; i += 256)
            sC[(i >> 8) * 257 + (i & 255)] = g_ctab[i];
    }
    __syncthreads();
    if (p >= HW) return;

    const int h = p / Wd;
    const int w = p - h * Wd;
    const int rcf = (h == 0) ? 0 : ((h == Hh - 1) ? 2 : 1);
    const int ccf = (w == 0) ? 0 : ((w == Wd - 1) ? 2 : 1);
    const int nvbase = 256 * (((rcf == 1) ? 3 : 2) * ((ccf == 1) ? 3 : 2));
    const int cbase = (rcf * 3 + ccf) * 257 + half * 128;

    uint32_t xr[72];
#pragma unroll
    for (int kh = 0; kh < 3; kh++) {
#pragma unroll
        for (int kw = 0; kw < 3; kw++) {
            const int tap = kh * 3 + kw;
            const int hh = h + kh - 1, ww = w + kw - 1;
            const bool v = ((unsigned)hh < (unsigned)Hh) && ((unsigned)ww < (unsigned)Wd);
            if (v) {
                const uint4 a0 = g_xbits[(b * HW + hh * Wd + ww) * 2 + 0];
                const uint4 a1 = g_xbits[(b * HW + hh * Wd + ww) * 2 + 1];
                xr[tap * 8 + 0] = a0.x; xr[tap * 8 + 1] = a0.y;
                xr[tap * 8 + 2] = a0.z; xr[tap * 8 + 3] = a0.w;
                xr[tap * 8 + 4] = a1.x; xr[tap * 8 + 5] = a1.y;
                xr[tap * 8 + 6] = a1.z; xr[tap * 8 + 7] = a1.w;
            } else {
#pragma unroll
                for (int j = 0; j < 8; j++) xr[tap * 8 + j] = 0u;
            }
        }
    }

    short* yout = g_y + ((size_t)(b * Cc + half * 128)) * HW + p;

#pragma unroll 1
    for (int o = 0; o < 128; o++) {
        const uint4* wp = ws4 + o * 18;

        // ---- direct path: words 0..31 (taps 0..3), POPC unit ----
        int P1 = 0;
#pragma unroll
        for (int j = 0; j < 8; j++) {
            const uint4 v = wp[j];
            P1 += __popc(xr[4 * j + 0] ^ v.x) + __popc(xr[4 * j + 1] ^ v.y)
                + __popc(xr[4 * j + 2] ^ v.z) + __popc(xr[4 * j + 3] ^ v.w);
        }

        // ---- CSA path: words 32..71 (taps 4..8) ----
        uint32_t d[40];
#pragma unroll
        for (int j = 0; j < 10; j++) {
            const uint4 v = wp[8 + j];
            d[4 * j + 0] = xr[32 + 4 * j + 0] ^ v.x;
            d[4 * j + 1] = xr[32 + 4 * j + 1] ^ v.y;
            d[4 * j + 2] = xr[32 + 4 * j + 2] ^ v.z;
            d[4 * j + 3] = xr[32 + 4 * j + 3] ^ v.w;
        }
        // L1: 13 FA over d[0..38], leftover d[39]
        uint32_t s1[13], c1[13];
#pragma unroll
        for (int g = 0; g < 13; g++)
            FAf(d[3 * g], d[3 * g + 1], d[3 * g + 2], s1[g], c1[g]);
        // weight-1 pool: s1[0..12] + d[39]  (14)
        uint32_t t0, t1, t2, t3, u0, u1, u2, u3;
        FAf(s1[0], s1[1], s1[2],  t0, u0);
        FAf(s1[3], s1[4], s1[5],  t1, u1);
        FAf(s1[6], s1[7], s1[8],  t2, u2);
        FAf(s1[9], s1[10], s1[11], t3, u3);
        uint32_t v0, z0, v1, z1;
        FAf(t0, t1, t2, v0, z0);
        FAf(t3, s1[12], d[39], v1, z1);
        // weight-2 pool: c1[0..12], u0..u3, z0, z1  (19)
        uint32_t e0, e1, e2, e3, e4, e5, f0, f1, f2, f3, f4, f5;
        FAf(c1[0], c1[1], c1[2],   e0, f0);
        FAf(c1[3], c1[4], c1[5],   e1, f1);
        FAf(c1[6], c1[7], c1[8],   e2, f2);
        FAf(c1[9], c1[10], c1[11], e3, f3);
        FAf(c1[12], u0, u1,        e4, f4);
        FAf(u2, u3, z0,            e5, f5);
        uint32_t g0, h0, g1, h1, k0, m0;
        FAf(e0, e1, e2, g0, h0);
        FAf(e3, e4, z1, g1, h1);
        FAf(g0, g1, e5, k0, m0);
        // weight-4 pool: f0..f5, h0, h1, m0  (9)
        uint32_t r0, n0, r1, n1, r2, n2, a4, b4;
        FAf(f0, f1, f2, r0, n0);
        FAf(f3, f4, f5, r1, n1);
        FAf(h0, h1, m0, r2, n2);
        FAf(r0, r1, r2, a4, b4);
        // weight-8 pool: n0, n1, n2, b4  (4)
        uint32_t a8, b8, s8, c8, s16, c16;
        FAf(n0, n1, n2, a8, b8);
        HAf(a8, b4, s8, c8);
        // weight-16: b8, c8
        HAf(b8, c8, s16, c16);

        int P = P1 + __popc(v0) + __popc(v1)
              + (__popc(k0)  << 1)
              + (__popc(a4)  << 2)
              + (__popc(s8)  << 3)
              + (__popc(s16) << 4)
              + (__popc(c16) << 5);
        int y = nvbase + 2 * sC[cbase + o] - 2 * P;
        yout[(size_t)o * HW] = (short)y;
    }
}

// ---------------------------------------------------------------------------
// Kernel 3b: BN statistics over y (exact integer sums)
// ---------------------------------------------------------------------------
__global__ void k_stats() {
    const int c = blockIdx.x, b = blockIdx.y;
    const int4* yp = (const int4*)(g_y + ((size_t)(b * Cc + c)) * HW);
    int       s  = 0;
    long long sq = 0;
    for (int i = threadIdx.x; i < HW / 8; i += 256) {
        int4 v = yp[i];
        const int ww[4] = {v.x, v.y, v.z, v.w};
#pragma unroll
        for (int j = 0; j < 4; j++) {
            int lo = (short)(ww[j] & 0xFFFF);
            int hi = (short)(((unsigned)ww[j]) >> 16);
            s  += lo + hi;
            sq += (long long)lo * lo + (long long)hi * hi;
        }
    }
#pragma unroll
    for (int off = 16; off > 0; off >>= 1) {
        s  += __shfl_down_sync(0xFFFFFFFFu, s,  off);
        sq += __shfl_down_sync(0xFFFFFFFFu, sq, off);
    }
    __shared__ int       wsum[8];
    __shared__ long long wsq[8];
    const int lane = threadIdx.x & 31, wid = threadIdx.x >> 5;
    if (lane == 0) { wsum[wid] = s; wsq[wid] = sq; }
    __syncthreads();
    if (wid == 0) {
        int       s2  = (lane < 8) ? wsum[lane] : 0;
        long long sq2 = (lane < 8) ? wsq[lane]  : 0;
#pragma unroll
        for (int off = 4; off > 0; off >>= 1) {
            s2  += __shfl_down_sync(0xFFFFFFFFu, s2,  off);
            sq2 += __shfl_down_sync(0xFFFFFFFFu, sq2, off);
        }
        if (lane == 0) {
            atomicAdd(&g_ysum[c],   (unsigned long long)(long long)s2);
            atomicAdd(&g_ysumsq[c], (unsigned long long)sq2);
        }
    }
}

// ---------------------------------------------------------------------------
// Kernel 4: BN finalize (inline) + apply + residual, vec4
// ---------------------------------------------------------------------------
__global__ void k_bn_add(const float* __restrict__ x,
                         const float* __restrict__ gamma,
                         const float* __restrict__ beta,
                         float* __restrict__ out) {
    size_t i4 = (size_t)blockIdx.x * 256 + threadIdx.x;
    if (i4 >= NELEM / 4) return;
    size_t base = i4 * 4;
    int c = (int)((base / HW) % Cc);
    const float ninv = 1.0f / (float)NPIX;
    float mean = (float)(long long)g_ysum[c] * ninv;
    float var  = (float)(long long)g_ysumsq[c] * ninv - mean * mean;
    float inv  = gamma[c] * rsqrtf(var + 1e-5f);
    float bias = beta[c] - mean * inv;
    short4 ys = ((const short4*)g_y)[i4];
    float4 xv = ((const float4*)x)[i4];
    float4 ov;
    ov.x = (float)ys.x * inv + bias + xv.x;
    ov.y = (float)ys.y * inv + bias + xv.y;
    ov.z = (float)ys.z * inv + bias + xv.z;
    ov.w = (float)ys.w * inv + bias + xv.w;
    ((float4*)out)[i4] = ov;
}

// ---------------------------------------------------------------------------
extern "C" void kernel_launch(void* const* d_in, const int* in_sizes, int n_in,
                              void* d_out, int out_size) {
    const float* x     = (const float*)d_in[0];
    const float* Wt    = (const float*)d_in[1];
    const float* gamma = (const float*)d_in[2];
    const float* beta  = (const float*)d_in[3];
    float* out = (float*)d_out;

    k_binarize_x<<<(NPIX + 255) / 256, 256>>>(x);
    k_binarize_w<<<(Cc * 9 * 8 + 255) / 256, 256>>>(Wt);
    k_prep_c<<<1, 256>>>();
    k_conv<<<dim3((HW + 255) / 256, 2, Bn), 256>>>();
    k_stats<<<dim3(Cc, Bn), 256>>>();
    k_bn_add<<<(unsigned)((NELEM / 4 + 255) / 256), 256>>>(x, gamma, beta, out);
}

// round 9
// speedup vs baseline: 3.0412x; 1.0805x over previous
#include <cuda_runtime.h>
#include <cstdint>

#define Bn 32
#define Cc 256
#define Hh 56
#define Wd 56
#define HW 3136
#define NPIX (Bn*HW)
#define NELEM ((size_t)Bn*Cc*HW)

// ---- device scratch ----
__device__ uint4              g_xbits[NPIX * 2];        // 8 u32 per pixel
__device__ uint32_t           g_wbits[Cc * 9 * 8];      // [o][tap][8]
__device__ int                g_ctab[9 * Cc];           // [cfg][o] border corrections
__device__ unsigned long long g_ysum[Cc];
__device__ unsigned long long g_ysumsq[Cc];
__device__ short              g_y[NELEM];               // NCHW int16 conv result

__device__ __forceinline__ void FAf(uint32_t a, uint32_t b, uint32_t c,
                                    uint32_t& s, uint32_t& cy) {
    s  = a ^ b ^ c;
    cy = (a & b) | (c & (a ^ b));
}
__device__ __forceinline__ void HAf(uint32_t a, uint32_t b,
                                    uint32_t& s, uint32_t& cy) {
    s = a ^ b; cy = a & b;
}

// ---------------------------------------------------------------------------
// Kernel 1: binarize x (NCHW) -> per-pixel 256-bit vectors
// ---------------------------------------------------------------------------
__global__ void k_binarize_x(const float* __restrict__ x) {
    int gp = blockIdx.x * 256 + threadIdx.x;
    if (gp >= NPIX) return;
    int b = gp / HW;
    int p = gp - b * HW;
    const float* xp = x + (size_t)b * Cc * HW + p;
    uint32_t wrd[8];
#pragma unroll
    for (int j = 0; j < 8; j++) {
        uint32_t v = 0;
#pragma unroll
        for (int l = 0; l < 32; l++) {
            float f = xp[(size_t)(j * 32 + l) * HW];
            v |= (f > 0.0f ? 1u : 0u) << l;
        }
        wrd[j] = v;
    }
    g_xbits[gp * 2 + 0] = make_uint4(wrd[0], wrd[1], wrd[2], wrd[3]);
    g_xbits[gp * 2 + 1] = make_uint4(wrd[4], wrd[5], wrd[6], wrd[7]);
}

// ---------------------------------------------------------------------------
// Kernel 2: binarize W (OIHW) + zero stat accumulators
// ---------------------------------------------------------------------------
__global__ void k_binarize_w(const float* __restrict__ Wt) {
    int idx = blockIdx.x * 256 + threadIdx.x;
    if (idx < Cc) { g_ysum[idx] = 0ull; g_ysumsq[idx] = 0ull; }
    if (idx >= Cc * 9 * 8) return;
    int j   = idx & 7;
    int tap = (idx >> 3) % 9;
    int o   = idx / 72;
    uint32_t v = 0;
#pragma unroll
    for (int l = 0; l < 32; l++) {
        int i = j * 32 + l;
        float f = Wt[((size_t)o * Cc + i) * 9 + tap];
        v |= (f > 0.0f ? 1u : 0u) << l;
    }
    g_wbits[idx] = v;
}

// ---------------------------------------------------------------------------
// Kernel 2b: per (border-config, outch) correction table
// ---------------------------------------------------------------------------
__global__ void k_prep_c() {
    int o = threadIdx.x;
    int ct[9];
#pragma unroll
    for (int t = 0; t < 9; t++) {
        int s = 0;
#pragma unroll
        for (int j = 0; j < 8; j++) s += __popc(g_wbits[o * 72 + t * 8 + j]);
        ct[t] = s;
    }
#pragma unroll
    for (int cfg = 0; cfg < 9; cfg++) {
        int rcf = cfg / 3, ccf = cfg % 3;
        int Cv = 0;
#pragma unroll
        for (int t = 0; t < 9; t++) {
            int kh = t / 3, kw = t % 3;
            bool inv = (rcf == 0 && kh == 0) || (rcf == 2 && kh == 2) ||
                       (ccf == 0 && kw == 0) || (ccf == 2 && kw == 2);
            if (inv) Cv += ct[t];
        }
        g_ctab[cfg * Cc + o] = Cv;
    }
}

// ---------------------------------------------------------------------------
// Kernel 3: XNOR conv — hybrid direct-POPC (taps 0..3) + CSA (taps 4..8)
// 128-thread blocks, 3 CTAs/SM -> 12 warps/SM
// ---------------------------------------------------------------------------
__global__ void __launch_bounds__(128, 3) k_conv() {
    const int p    = blockIdx.x * 128 + threadIdx.x;
    const int half = blockIdx.y;
    const int b    = blockIdx.z;

    __shared__ uint4 ws4[128 * 18];
    __shared__ int   sC[9 * 257];
    {
        const uint4* src = (const uint4*)(g_wbits + half * 128 * 72);
        for (int i = threadIdx.x; i < 128 * 18; i += 128) ws4[i] = src[i];
        for (int i = threadIdx.x; i < 9 * 256; i += 128)
            sC[(i >> 8) * 257 + (i & 255)] = g_ctab[i];
    }
    __syncthreads();
    if (p >= HW) return;

    const int h = p / Wd;
    const int w = p - h * Wd;
    const int rcf = (h == 0) ? 0 : ((h == Hh - 1) ? 2 : 1);
    const int ccf = (w == 0) ? 0 : ((w == Wd - 1) ? 2 : 1);
    const int nvbase = 256 * (((rcf == 1) ? 3 : 2) * ((ccf == 1) ? 3 : 2));
    const int cbase = (rcf * 3 + ccf) * 257 + half * 128;

    uint32_t xr[72];
#pragma unroll
    for (int kh = 0; kh < 3; kh++) {
#pragma unroll
        for (int kw = 0; kw < 3; kw++) {
            const int tap = kh * 3 + kw;
            const int hh = h + kh - 1, ww = w + kw - 1;
            const bool v = ((unsigned)hh < (unsigned)Hh) && ((unsigned)ww < (unsigned)Wd);
            if (v) {
                const uint4 a0 = g_xbits[(b * HW + hh * Wd + ww) * 2 + 0];
                const uint4 a1 = g_xbits[(b * HW + hh * Wd + ww) * 2 + 1];
                xr[tap * 8 + 0] = a0.x; xr[tap * 8 + 1] = a0.y;
                xr[tap * 8 + 2] = a0.z; xr[tap * 8 + 3] = a0.w;
                xr[tap * 8 + 4] = a1.x; xr[tap * 8 + 5] = a1.y;
                xr[tap * 8 + 6] = a1.z; xr[tap * 8 + 7] = a1.w;
            } else {
#pragma unroll
                for (int j = 0; j < 8; j++) xr[tap * 8 + j] = 0u;
            }
        }
    }

    short* yout = g_y + ((size_t)(b * Cc + half * 128)) * HW + p;

#pragma unroll 1
    for (int o = 0; o < 128; o++) {
        const uint4* wp = ws4 + o * 18;

        // ---- direct path: words 0..31 (taps 0..3), POPC unit ----
        int P1 = 0;
#pragma unroll
        for (int j = 0; j < 8; j++) {
            const uint4 v = wp[j];
            P1 += __popc(xr[4 * j + 0] ^ v.x) + __popc(xr[4 * j + 1] ^ v.y)
                + __popc(xr[4 * j + 2] ^ v.z) + __popc(xr[4 * j + 3] ^ v.w);
        }

        // ---- CSA path: words 32..71 (taps 4..8) ----
        uint32_t d[40];
#pragma unroll
        for (int j = 0; j < 10; j++) {
            const uint4 v = wp[8 + j];
            d[4 * j + 0] = xr[32 + 4 * j + 0] ^ v.x;
            d[4 * j + 1] = xr[32 + 4 * j + 1] ^ v.y;
            d[4 * j + 2] = xr[32 + 4 * j + 2] ^ v.z;
            d[4 * j + 3] = xr[32 + 4 * j + 3] ^ v.w;
        }
        uint32_t s1[13], c1[13];
#pragma unroll
        for (int g = 0; g < 13; g++)
            FAf(d[3 * g], d[3 * g + 1], d[3 * g + 2], s1[g], c1[g]);
        uint32_t t0, t1, t2, t3, u0, u1, u2, u3;
        FAf(s1[0], s1[1], s1[2],  t0, u0);
        FAf(s1[3], s1[4], s1[5],  t1, u1);
        FAf(s1[6], s1[7], s1[8],  t2, u2);
        FAf(s1[9], s1[10], s1[11], t3, u3);
        uint32_t v0, z0, v1, z1;
        FAf(t0, t1, t2, v0, z0);
        FAf(t3, s1[12], d[39], v1, z1);
        uint32_t e0, e1, e2, e3, e4, e5, f0, f1, f2, f3, f4, f5;
        FAf(c1[0], c1[1], c1[2],   e0, f0);
        FAf(c1[3], c1[4], c1[5],   e1, f1);
        FAf(c1[6], c1[7], c1[8],   e2, f2);
        FAf(c1[9], c1[10], c1[11], e3, f3);
        FAf(c1[12], u0, u1,        e4, f4);
        FAf(u2, u3, z0,            e5, f5);
        uint32_t g0, h0, g1, h1, k0, m0;
        FAf(e0, e1, e2, g0, h0);
        FAf(e3, e4, z1, g1, h1);
        FAf(g0, g1, e5, k0, m0);
        uint32_t r0, n0, r1, n1, r2, n2, a4, b4;
        FAf(f0, f1, f2, r0, n0);
        FAf(f3, f4, f5, r1, n1);
        FAf(h0, h1, m0, r2, n2);
        FAf(r0, r1, r2, a4, b4);
        uint32_t a8, b8, s8, c8, s16, c16;
        FAf(n0, n1, n2, a8, b8);
        HAf(a8, b4, s8, c8);
        HAf(b8, c8, s16, c16);

        int P = P1 + __popc(v0) + __popc(v1)
              + (__popc(k0)  << 1)
              + (__popc(a4)  << 2)
              + (__popc(s8)  << 3)
              + (__popc(s16) << 4)
              + (__popc(c16) << 5);
        int y = nvbase + 2 * sC[cbase + o] - 2 * P;
        yout[(size_t)o * HW] = (short)y;
    }
}

// ---------------------------------------------------------------------------
// Kernel 3b: BN statistics over y (exact integer sums)
// ---------------------------------------------------------------------------
__global__ void k_stats() {
    const int c = blockIdx.x, b = blockIdx.y;
    const int4* yp = (const int4*)(g_y + ((size_t)(b * Cc + c)) * HW);
    int       s  = 0;
    long long sq = 0;
    for (int i = threadIdx.x; i < HW / 8; i += 256) {
        int4 v = yp[i];
        const int ww[4] = {v.x, v.y, v.z, v.w};
#pragma unroll
        for (int j = 0; j < 4; j++) {
            int lo = (short)(ww[j] & 0xFFFF);
            int hi = (short)(((unsigned)ww[j]) >> 16);
            s  += lo + hi;
            sq += (long long)lo * lo + (long long)hi * hi;
        }
    }
#pragma unroll
    for (int off = 16; off > 0; off >>= 1) {
        s  += __shfl_down_sync(0xFFFFFFFFu, s,  off);
        sq += __shfl_down_sync(0xFFFFFFFFu, sq, off);
    }
    __shared__ int       wsum[8];
    __shared__ long long wsq[8];
    const int lane = threadIdx.x & 31, wid = threadIdx.x >> 5;
    if (lane == 0) { wsum[wid] = s; wsq[wid] = sq; }
    __syncthreads();
    if (wid == 0) {
        int       s2  = (lane < 8) ? wsum[lane] : 0;
        long long sq2 = (lane < 8) ? wsq[lane]  : 0;
#pragma unroll
        for (int off = 4; off > 0; off >>= 1) {
            s2  += __shfl_down_sync(0xFFFFFFFFu, s2,  off);
            sq2 += __shfl_down_sync(0xFFFFFFFFu, sq2, off);
        }
        if (lane == 0) {
            atomicAdd(&g_ysum[c],   (unsigned long long)(long long)s2);
            atomicAdd(&g_ysumsq[c], (unsigned long long)sq2);
        }
    }
}

// ---------------------------------------------------------------------------
// Kernel 4: BN finalize (inline) + apply + residual, vec4
// ---------------------------------------------------------------------------
__global__ void k_bn_add(const float* __restrict__ x,
                         const float* __restrict__ gamma,
                         const float* __restrict__ beta,
                         float* __restrict__ out) {
    size_t i4 = (size_t)blockIdx.x * 256 + threadIdx.x;
    if (i4 >= NELEM / 4) return;
    size_t base = i4 * 4;
    int c = (int)((base / HW) % Cc);
    const float ninv = 1.0f / (float)NPIX;
    float mean = (float)(long long)g_ysum[c] * ninv;
    float var  = (float)(long long)g_ysumsq[c] * ninv - mean * mean;
    float inv  = gamma[c] * rsqrtf(var + 1e-5f);
    float bias = beta[c] - mean * inv;
    short4 ys = ((const short4*)g_y)[i4];
    float4 xv = ((const float4*)x)[i4];
    float4 ov;
    ov.x = (float)ys.x * inv + bias + xv.x;
    ov.y = (float)ys.y * inv + bias + xv.y;
    ov.z = (float)ys.z * inv + bias + xv.z;
    ov.w = (float)ys.w * inv + bias + xv.w;
    ((float4*)out)[i4] = ov;
}

// ---------------------------------------------------------------------------
extern "C" void kernel_launch(void* const* d_in, const int* in_sizes, int n_in,
                              void* d_out, int out_size) {
    const float* x     = (const float*)d_in[0];
    const float* Wt    = (const float*)d_in[1];
    const float* gamma = (const float*)d_in[2];
    const float* beta  = (const float*)d_in[3];
    float* out = (float*)d_out;

    k_binarize_x<<<(NPIX + 255) / 256, 256>>>(x);
    k_binarize_w<<<(Cc * 9 * 8 + 255) / 256, 256>>>(Wt);
    k_prep_c<<<1, 256>>>();
    k_conv<<<dim3((HW + 127) / 128, 2, Bn), 128>>>();
    k_stats<<<dim3(Cc, Bn), 256>>>();
    k_bn_add<<<(unsigned)((NELEM / 4 + 255) / 256), 256>>>(x, gamma, beta, out);
}